// round 10
// baseline (speedup 1.0000x reference)
#include <cuda_runtime.h>
#include <cuda_fp16.h>
#include <math.h>
#include <cstdint>

#define BDIM 16
#define TDIM 2048
#define CDIM 1024
#define HDIM 64
#define MROWS (BDIM * TDIM)   // 32768

// fp16 scratch (device globals: no allocations).
__device__ __align__(16) __half g_Qh[MROWS * HDIM];                // [t][h'] interleaved, pre-scaled
__device__ __align__(16) __half g_Kh[MROWS * HDIM];                // [t][h'] interleaved
__device__ __align__(16) __half g_Vh[(size_t)BDIM * HDIM * TDIM];  // [b][h][t'] interleaved
__device__ __align__(16) __half g_Wh[192 * CDIM];                  // [n][k'] interleaved

// pair interleave within 16-groups: x=(a+8b+16c), a<8,b<2 -> 4*((a>>1)&3)+(a&1)+2b+16c
static __device__ __forceinline__ int ih(int x) {
    return 4 * ((x >> 1) & 3) + (x & 1) + 2 * ((x >> 3) & 1) + (x & ~15);
}
static __device__ __forceinline__ uint32_t h2u(float lo, float hi) {
    __half2 h = __floats2half2_rn(lo, hi);
    return *(uint32_t*)&h;
}
static __device__ __forceinline__ uint32_t smem_u32(const void* p) {
    uint32_t a;
    asm("{ .reg .u64 t; cvta.to.shared.u64 t, %1; cvt.u32.u64 %0, t; }" : "=r"(a) : "l"(p));
    return a;
}
static __device__ __forceinline__ void cp16(uint32_t saddr, const void* g) {
    asm volatile("cp.async.ca.shared.global [%0], [%1], 16;" :: "r"(saddr), "l"(g));
}

#define MMA_F16(d, a, b0_, b1_) \
    asm volatile( \
        "mma.sync.aligned.m16n8k16.row.col.f32.f16.f16.f32 " \
        "{%0,%1,%2,%3}, {%4,%5,%6,%7}, {%8,%9}, {%0,%1,%2,%3};" \
        : "+f"((d)[0]), "+f"((d)[1]), "+f"((d)[2]), "+f"((d)[3]) \
        : "r"((a)[0]), "r"((a)[1]), "r"((a)[2]), "r"((a)[3]), \
          "r"(b0_), "r"(b1_))

// ---------------------------------------------------------------------------
// Kernel 0: convert weights to fp16 [n][k'] interleaved — coalesced transpose.
// Grid: 3 matrices x 8 k-blocks of 128. Block 256 threads.
// ---------------------------------------------------------------------------
__global__ __launch_bounds__(256) void cvt_w(
    const float* __restrict__ wq,
    const float* __restrict__ wk,
    const float* __restrict__ wv)
{
    __shared__ float ws[128][65];        // [k][n] padded

    const int widx = blockIdx.x >> 3;
    const int kblk = (blockIdx.x & 7) * 128;
    const float* wp = (widx == 0) ? wq : ((widx == 1) ? wk : wv);

    #pragma unroll
    for (int i = 0; i < 8; i++) {
        int idx = threadIdx.x + i * 256;       // 2048 float4 (128 rows x 16)
        int r = idx >> 4, c4 = idx & 15;
        float4 v = *(const float4*)&wp[(size_t)(kblk + r) * HDIM + c4 * 4];
        ws[r][c4 * 4 + 0] = v.x;
        ws[r][c4 * 4 + 1] = v.y;
        ws[r][c4 * 4 + 2] = v.z;
        ws[r][c4 * 4 + 3] = v.w;
    }
    __syncthreads();

    #pragma unroll
    for (int i = 0; i < 16; i++) {
        int idx = threadIdx.x + i * 256;       // 4096 half2 (64 n x 64 k-pairs)
        int nn = idx >> 6, kp = idx & 63;
        int kl = kp * 2;                       // local k (even): ih(k+1)=ih(k)+1
        *(__half2*)&g_Wh[(size_t)(widx * 64 + nn) * CDIM + ih(kblk + kl)] =
            __floats2half2_rn(ws[kl][nn], ws[kl + 1][nn]);
    }
}

// ---------------------------------------------------------------------------
// Kernel 1: QKV projection, fp16 m16n8k16.
// CTA 64x192, K-chunk 32, 128 threads (4 warps, warp tile 32x96), 3 CTAs/SM.
// ---------------------------------------------------------------------------
#define XSTR 48                      // smem row stride in halfs
#define PA_H (64 * XSTR)             // A stage halfs (3072)
#define PB_H (192 * XSTR)            // B stage halfs (9216)
#define PROJ_SMEM ((2 * PA_H + 2 * PB_H) * 2)   // 49152 B
#define NCH (CDIM / 32)              // 32 chunks

__global__ __launch_bounds__(128, 3) void qkv_proj_f16(const float* __restrict__ x)
{
    extern __shared__ __half smh[];
    __half* Ax = smh;                // [2][64*48]
    __half* Bw = smh + 2 * PA_H;     // [2][192*48]

    const int tid  = threadIdx.x;
    const int wid  = tid >> 5;
    const int lane = tid & 31;
    const int gid  = lane >> 2;
    const int tg   = lane & 3;
    const int wm   = (wid & 1) * 32;
    const int wn   = (wid >> 1) * 96;
    const int m0   = blockIdx.x * 64;
    const uint32_t bwb = smem_u32(Bw);

    float acc[2][12][4];
    #pragma unroll
    for (int mi = 0; mi < 2; mi++)
        #pragma unroll
        for (int ni = 0; ni < 12; ni++)
            #pragma unroll
            for (int k = 0; k < 4; k++) acc[mi][ni][k] = 0.f;

    float4 ra[4];

    auto gloadA = [&](int c) {
        #pragma unroll
        for (int i = 0; i < 4; i++) {
            int idx = tid + i * 128;             // 512 float4 (64 x 8)
            int row = idx >> 3, c4 = idx & 7;
            ra[i] = *(const float4*)&x[(size_t)(m0 + row) * CDIM + c * 32 + c4 * 4];
        }
    };
    auto sstoreA = [&](int s) {
        #pragma unroll
        for (int i = 0; i < 4; i++) {
            int idx = tid + i * 128;
            int row = idx >> 3, c4 = idx & 7;
            int k = c4 * 4;
            __half* base = Ax + s * PA_H + row * XSTR;
            *(__half2*)&base[ih(k)]     = __floats2half2_rn(ra[i].x, ra[i].y);
            *(__half2*)&base[ih(k + 2)] = __floats2half2_rn(ra[i].z, ra[i].w);
        }
    };
    auto cpB = [&](int c, int s) {
        #pragma unroll
        for (int i = 0; i < 6; i++) {
            int idx = tid + i * 128;             // 768 16B chunks (192 rows x 4)
            int row = idx >> 2, cc = idx & 3;
            cp16(bwb + s * (PB_H * 2) + row * (XSTR * 2) + cc * 16,
                 g_Wh + (size_t)row * CDIM + c * 32 + cc * 8);
        }
    };

    gloadA(0);
    cpB(0, 0);
    asm volatile("cp.async.commit_group;");
    sstoreA(0);

    for (int c = 0; c < NCH; c++) {
        const int s = c & 1;
        if (c + 1 < NCH) {
            gloadA(c + 1);
            cpB(c + 1, s ^ 1);
            asm volatile("cp.async.commit_group;");
        }
        if (c + 1 < NCH) { asm volatile("cp.async.wait_group 1;" ::: "memory"); }
        else             { asm volatile("cp.async.wait_group 0;" ::: "memory"); }
        __syncthreads();

        const __half* As = Ax + s * PA_H;
        const __half* Bs = Bw + s * PB_H;
        #pragma unroll
        for (int kb = 0; kb < 2; kb++) {
            uint32_t a[2][4];
            #pragma unroll
            for (int mi = 0; mi < 2; mi++) {
                int row = wm + mi * 16 + gid;
                uint2 lo = *(const uint2*)&As[row * XSTR + kb * 16 + tg * 4];
                uint2 hi = *(const uint2*)&As[(row + 8) * XSTR + kb * 16 + tg * 4];
                a[mi][0] = lo.x; a[mi][1] = hi.x; a[mi][2] = lo.y; a[mi][3] = hi.y;
            }
            #pragma unroll
            for (int ni = 0; ni < 12; ni++) {
                uint2 bb = *(const uint2*)&Bs[(wn + ni * 8 + gid) * XSTR + kb * 16 + tg * 4];
                MMA_F16(acc[0][ni], a[0], bb.x, bb.y);
                MMA_F16(acc[1][ni], a[1], bb.x, bb.y);
            }
        }

        if (c + 1 < NCH) sstoreA(s ^ 1);
        __syncthreads();
    }

    // ---- epilogue: stage fp16 tiles (aliasing smem), coalesced copy out
    __half* stQ = smh;            // [t 64][h' 64]
    __half* stK = smh + 4096;
    __half* stV = smh + 8192;     // [h 64][t' 64]

    __syncthreads();
    #pragma unroll
    for (int mi = 0; mi < 2; mi++) {
        #pragma unroll
        for (int ni = 0; ni < 12; ni++) {
            const int n   = wn + ni * 8 + tg * 2;
            const int sec = n >> 6;
            const int h   = n & 63;
            const int tl  = wm + mi * 16 + gid;
            float a0 = acc[mi][ni][0], a1 = acc[mi][ni][1];
            float a2 = acc[mi][ni][2], a3 = acc[mi][ni][3];
            if (sec == 2) {                      // V: transpose + t-interleave
                const int x0 = ih(tl), x1 = ih(tl + 8);
                stV[h * 64 + x0]       = __float2half(a0);
                stV[(h + 1) * 64 + x0] = __float2half(a1);
                stV[h * 64 + x1]       = __float2half(a2);
                stV[(h + 1) * 64 + x1] = __float2half(a3);
            } else {                             // Q/K: [t][h'] pair-interleaved
                __half* st = (sec == 0) ? stQ : stK;
                const float sc = (sec == 0) ? 0.125f : 1.0f;
                const int hp = ih(h);
                *(__half2*)&st[tl * 64 + hp]       = __floats2half2_rn(a0 * sc, a1 * sc);
                *(__half2*)&st[(tl + 8) * 64 + hp] = __floats2half2_rn(a2 * sc, a3 * sc);
            }
        }
    }
    __syncthreads();

    const int bb = m0 / TDIM;
    const int t0 = m0 % TDIM;
    #pragma unroll
    for (int i = 0; i < 4; i++) {
        int idx = tid + i * 128;                 // 512 uint4 chunks (64 x 8)
        int row = idx >> 3, c = idx & 7;
        *(uint4*)(g_Qh + (size_t)(m0 + row) * 64 + c * 8) =
            *(uint4*)(stQ + row * 64 + c * 8);
        *(uint4*)(g_Kh + (size_t)(m0 + row) * 64 + c * 8) =
            *(uint4*)(stK + row * 64 + c * 8);
        *(uint4*)(g_Vh + ((size_t)bb * 64 + row) * TDIM + t0 + c * 8) =
            *(uint4*)(stV + row * 64 + c * 8);
    }
}

// ---------------------------------------------------------------------------
// Kernel 2: flash attention, fp16 m16n8k16, P in registers (R7-validated).
// ---------------------------------------------------------------------------
#define KVS 80

__global__ __launch_bounds__(128, 4) void attn_f16(float* __restrict__ out)
{
    __shared__ __half Ks[64 * KVS];   // [j][h']  10 KB
    __shared__ __half Vs[64 * KVS];   // [h][j']  10 KB

    const int b    = blockIdx.y;
    const int qt   = gridDim.x - 1 - blockIdx.x;   // heavy q-tiles first
    const int tid  = threadIdx.x;
    const int wid  = tid >> 5;
    const int lane = tid & 31;
    const int gid  = lane >> 2;
    const int tg   = lane & 3;
    const int wm   = wid * 16;
    const int q0   = qt * 64;
    const int row0 = q0 + wm + gid;

    uint32_t qa[4][4];
    {
        const __half* Qh = g_Qh + ((size_t)b * TDIM + q0 + wm) * 64;
        #pragma unroll
        for (int kb = 0; kb < 4; kb++) {
            uint2 lo = *(const uint2*)(Qh + gid * 64 + 16 * kb + 4 * tg);
            uint2 hi = *(const uint2*)(Qh + (gid + 8) * 64 + 16 * kb + 4 * tg);
            qa[kb][0] = lo.x; qa[kb][1] = hi.x; qa[kb][2] = lo.y; qa[kb][3] = hi.y;
        }
    }

    float o[8][4];
    #pragma unroll
    for (int n = 0; n < 8; n++)
        #pragma unroll
        for (int k = 0; k < 4; k++) o[n][k] = 0.f;
    float m0r = -INFINITY, m1r = -INFINITY;
    float l0 = 0.f, l1 = 0.f;

    const uint32_t ksb = smem_u32(Ks);
    const uint32_t vsb = smem_u32(Vs);
    const int ntiles = qt + 1;

    for (int kt = 0; kt < ntiles; kt++) {
        const int kv0 = kt * 64;

        __syncthreads();
        {
            const __half* Kg = g_Kh + ((size_t)b * TDIM + kv0) * 64;
            const __half* Vg = g_Vh + (size_t)b * 64 * TDIM + kv0;
            #pragma unroll
            for (int i = 0; i < 4; i++) {
                int idx = tid + i * 128;
                int row = idx >> 3, c = idx & 7;
                cp16(ksb + row * (KVS * 2) + c * 16, Kg + (size_t)row * 64 + c * 8);
                cp16(vsb + row * (KVS * 2) + c * 16, Vg + (size_t)row * TDIM + c * 8);
            }
        }
        asm volatile("cp.async.commit_group;");
        asm volatile("cp.async.wait_group 0;" ::: "memory");
        __syncthreads();

        float s[8][4];
        #pragma unroll
        for (int n = 0; n < 8; n++) {
            s[n][0] = s[n][1] = s[n][2] = s[n][3] = 0.f;
            #pragma unroll
            for (int k = 0; k < 4; k++) {
                uint2 bb = *(const uint2*)(Ks + (n * 8 + gid) * KVS + 16 * k + 4 * tg);
                MMA_F16(s[n], qa[k], bb.x, bb.y);
            }
        }

        if (kt == qt) {
            #pragma unroll
            for (int n = 0; n < 8; n++) {
                int j0 = kv0 + n * 8 + 2 * tg;
                if (j0     > row0)     s[n][0] = -1e30f;
                if (j0 + 1 > row0)     s[n][1] = -1e30f;
                if (j0     > row0 + 8) s[n][2] = -1e30f;
                if (j0 + 1 > row0 + 8) s[n][3] = -1e30f;
            }
        }

        float tm0 = -INFINITY, tm1 = -INFINITY;
        #pragma unroll
        for (int n = 0; n < 8; n++) {
            tm0 = fmaxf(tm0, fmaxf(s[n][0], s[n][1]));
            tm1 = fmaxf(tm1, fmaxf(s[n][2], s[n][3]));
        }
        tm0 = fmaxf(tm0, __shfl_xor_sync(0xFFFFFFFFu, tm0, 1));
        tm0 = fmaxf(tm0, __shfl_xor_sync(0xFFFFFFFFu, tm0, 2));
        tm1 = fmaxf(tm1, __shfl_xor_sync(0xFFFFFFFFu, tm1, 1));
        tm1 = fmaxf(tm1, __shfl_xor_sync(0xFFFFFFFFu, tm1, 2));

        const float mn0 = fmaxf(m0r, tm0);
        const float mn1 = fmaxf(m1r, tm1);
        const float c0  = __expf(m0r - mn0);
        const float c1  = __expf(m1r - mn1);
        l0 *= c0;  l1 *= c1;
        #pragma unroll
        for (int n = 0; n < 8; n++) {
            o[n][0] *= c0; o[n][1] *= c0;
            o[n][2] *= c1; o[n][3] *= c1;
        }
        m0r = mn0;  m1r = mn1;

        uint32_t pa[4][4];
        #pragma unroll
        for (int n = 0; n < 8; n++) {
            float p0 = __expf(s[n][0] - mn0);
            float p1 = __expf(s[n][1] - mn0);
            float p2 = __expf(s[n][2] - mn1);
            float p3 = __expf(s[n][3] - mn1);
            l0 += p0 + p1;
            l1 += p2 + p3;
            const int kl = n >> 1;
            if ((n & 1) == 0) { pa[kl][0] = h2u(p0, p1); pa[kl][1] = h2u(p2, p3); }
            else              { pa[kl][2] = h2u(p0, p1); pa[kl][3] = h2u(p2, p3); }
        }

        #pragma unroll
        for (int n = 0; n < 8; n++) {
            #pragma unroll
            for (int kl = 0; kl < 4; kl++) {
                uint2 bb = *(const uint2*)(Vs + (n * 8 + gid) * KVS + 16 * kl + 4 * tg);
                MMA_F16(o[n], pa[kl], bb.x, bb.y);
            }
        }
    }

    l0 += __shfl_xor_sync(0xFFFFFFFFu, l0, 1);
    l0 += __shfl_xor_sync(0xFFFFFFFFu, l0, 2);
    l1 += __shfl_xor_sync(0xFFFFFFFFu, l1, 1);
    l1 += __shfl_xor_sync(0xFFFFFFFFu, l1, 2);
    const float i0 = 1.f / l0;
    const float i1 = 1.f / l1;

    float* ob = out + ((size_t)b * TDIM + q0 + wm) * HDIM;
    #pragma unroll
    for (int n = 0; n < 8; n++) {
        *(float2*)&ob[gid * HDIM + n * 8 + 2 * tg] =
            make_float2(o[n][0] * i0, o[n][1] * i0);
        *(float2*)&ob[(gid + 8) * HDIM + n * 8 + 2 * tg] =
            make_float2(o[n][2] * i1, o[n][3] * i1);
    }
}

// ---------------------------------------------------------------------------
extern "C" void kernel_launch(void* const* d_in, const int* in_sizes, int n_in,
                              void* d_out, int out_size)
{
    const float* x  = (const float*)d_in[0];
    const float* wq = (const float*)d_in[1];
    const float* wk = (const float*)d_in[2];
    const float* wv = (const float*)d_in[3];
    float* out = (float*)d_out;

    cvt_w<<<24, 256>>>(wq, wk, wv);

    cudaFuncSetAttribute(qkv_proj_f16, cudaFuncAttributeMaxDynamicSharedMemorySize, PROJ_SMEM);
    qkv_proj_f16<<<MROWS / 64, 128, PROJ_SMEM>>>(x);

    attn_f16<<<dim3(TDIM / 64, BDIM), 128>>>(out);
}

// round 11
// speedup vs baseline: 1.0203x; 1.0203x over previous
#include <cuda_runtime.h>
#include <cuda_fp16.h>
#include <math.h>
#include <cstdint>

#define BDIM 16
#define TDIM 2048
#define CDIM 1024
#define HDIM 64
#define MROWS (BDIM * TDIM)   // 32768

// fp16 scratch (device globals: no allocations).
__device__ __align__(16) __half g_Qh[MROWS * HDIM];                // [t][h'] interleaved, pre-scaled
__device__ __align__(16) __half g_Kh[MROWS * HDIM];                // [t][h'] interleaved
__device__ __align__(16) __half g_Vh[(size_t)BDIM * HDIM * TDIM];  // [b][h][t'] interleaved
__device__ __align__(16) __half g_Wh[192 * CDIM];                  // [n][k'] interleaved

// pair interleave within 16-groups: x=(a+8b+16c), a<8,b<2 -> 4*((a>>1)&3)+(a&1)+2b+16c
static __device__ __forceinline__ int ih(int x) {
    return 4 * ((x >> 1) & 3) + (x & 1) + 2 * ((x >> 3) & 1) + (x & ~15);
}
static __device__ __forceinline__ uint32_t h2u(float lo, float hi) {
    __half2 h = __floats2half2_rn(lo, hi);
    return *(uint32_t*)&h;
}
static __device__ __forceinline__ uint32_t smem_u32(const void* p) {
    uint32_t a;
    asm("{ .reg .u64 t; cvta.to.shared.u64 t, %1; cvt.u32.u64 %0, t; }" : "=r"(a) : "l"(p));
    return a;
}
static __device__ __forceinline__ void cp16(uint32_t saddr, const void* g) {
    asm volatile("cp.async.ca.shared.global [%0], [%1], 16;" :: "r"(saddr), "l"(g));
}

#define MMA_F16(d, a, b0_, b1_) \
    asm volatile( \
        "mma.sync.aligned.m16n8k16.row.col.f32.f16.f16.f32 " \
        "{%0,%1,%2,%3}, {%4,%5,%6,%7}, {%8,%9}, {%0,%1,%2,%3};" \
        : "+f"((d)[0]), "+f"((d)[1]), "+f"((d)[2]), "+f"((d)[3]) \
        : "r"((a)[0]), "r"((a)[1]), "r"((a)[2]), "r"((a)[3]), \
          "r"(b0_), "r"(b1_))

// ---------------------------------------------------------------------------
// Kernel 0: convert weights to fp16 [n][k'] interleaved — coalesced transpose.
// ---------------------------------------------------------------------------
__global__ __launch_bounds__(256) void cvt_w(
    const float* __restrict__ wq,
    const float* __restrict__ wk,
    const float* __restrict__ wv)
{
    __shared__ float ws[128][65];        // [k][n] padded

    const int widx = blockIdx.x >> 3;
    const int kblk = (blockIdx.x & 7) * 128;
    const float* wp = (widx == 0) ? wq : ((widx == 1) ? wk : wv);

    #pragma unroll
    for (int i = 0; i < 8; i++) {
        int idx = threadIdx.x + i * 256;       // 2048 float4 (128 rows x 16)
        int r = idx >> 4, c4 = idx & 15;
        float4 v = *(const float4*)&wp[(size_t)(kblk + r) * HDIM + c4 * 4];
        ws[r][c4 * 4 + 0] = v.x;
        ws[r][c4 * 4 + 1] = v.y;
        ws[r][c4 * 4 + 2] = v.z;
        ws[r][c4 * 4 + 3] = v.w;
    }
    __syncthreads();

    #pragma unroll
    for (int i = 0; i < 16; i++) {
        int idx = threadIdx.x + i * 256;       // 4096 half2 (64 n x 64 k-pairs)
        int nn = idx >> 6, kp = idx & 63;
        int kl = kp * 2;                       // even k: ih(k+1)=ih(k)+1
        *(__half2*)&g_Wh[(size_t)(widx * 64 + nn) * CDIM + ih(kblk + kl)] =
            __floats2half2_rn(ws[kl][nn], ws[kl + 1][nn]);
    }
}

// ---------------------------------------------------------------------------
// Kernel 1: QKV projection, fp16 m16n8k16 — R8 config (128x192, 256 thr).
// ---------------------------------------------------------------------------
#define XSTR 48                      // smem row stride in halfs
#define PA_H (128 * XSTR)            // A stage halfs (6144)
#define PB_H (192 * XSTR)            // B stage halfs (9216)
#define PROJ_SMEM ((2 * PA_H + 2 * PB_H) * 2)   // 61440 B
#define NCH (CDIM / 32)              // 32 chunks

__global__ __launch_bounds__(256) void qkv_proj_f16(const float* __restrict__ x)
{
    extern __shared__ __half smh[];
    __half* Ax = smh;                // [2][128*48]
    __half* Bw = smh + 2 * PA_H;     // [2][192*48]

    const int tid  = threadIdx.x;
    const int wid  = tid >> 5;
    const int lane = tid & 31;
    const int gid  = lane >> 2;
    const int tg   = lane & 3;
    const int wm   = (wid >> 1) * 32;
    const int wn   = (wid & 1) * 96;
    const int m0   = blockIdx.x * 128;
    const uint32_t bwb = smem_u32(Bw);

    float acc[2][12][4];
    #pragma unroll
    for (int mi = 0; mi < 2; mi++)
        #pragma unroll
        for (int ni = 0; ni < 12; ni++)
            #pragma unroll
            for (int k = 0; k < 4; k++) acc[mi][ni][k] = 0.f;

    float4 ra[4];

    auto gloadA = [&](int c) {
        #pragma unroll
        for (int i = 0; i < 4; i++) {
            int idx = tid + i * 256;             // 1024 float4 slots (128x32)
            int row = idx >> 3, c4 = idx & 7;
            ra[i] = *(const float4*)&x[(size_t)(m0 + row) * CDIM + c * 32 + c4 * 4];
        }
    };
    auto sstoreA = [&](int s) {
        #pragma unroll
        for (int i = 0; i < 4; i++) {
            int idx = tid + i * 256;
            int row = idx >> 3, c4 = idx & 7;
            int k = c4 * 4;
            __half* base = Ax + s * PA_H + row * XSTR;
            *(__half2*)&base[ih(k)]     = __floats2half2_rn(ra[i].x, ra[i].y);
            *(__half2*)&base[ih(k + 2)] = __floats2half2_rn(ra[i].z, ra[i].w);
        }
    };
    auto cpB = [&](int c, int s) {
        #pragma unroll
        for (int i = 0; i < 3; i++) {
            int idx = tid + i * 256;             // 768 16B chunks (192 rows x 4)
            int row = idx >> 2, cc = idx & 3;
            cp16(bwb + s * (PB_H * 2) + row * (XSTR * 2) + cc * 16,
                 g_Wh + (size_t)row * CDIM + c * 32 + cc * 8);
        }
    };

    gloadA(0);
    cpB(0, 0);
    asm volatile("cp.async.commit_group;");
    sstoreA(0);

    for (int c = 0; c < NCH; c++) {
        const int s = c & 1;
        if (c + 1 < NCH) {
            gloadA(c + 1);
            cpB(c + 1, s ^ 1);
            asm volatile("cp.async.commit_group;");
        }
        if (c + 1 < NCH) { asm volatile("cp.async.wait_group 1;" ::: "memory"); }
        else             { asm volatile("cp.async.wait_group 0;" ::: "memory"); }
        __syncthreads();

        const __half* As = Ax + s * PA_H;
        const __half* Bs = Bw + s * PB_H;
        #pragma unroll
        for (int kb = 0; kb < 2; kb++) {
            uint32_t a[2][4];
            #pragma unroll
            for (int mi = 0; mi < 2; mi++) {
                int row = wm + mi * 16 + gid;
                uint2 lo = *(const uint2*)&As[row * XSTR + kb * 16 + tg * 4];
                uint2 hi = *(const uint2*)&As[(row + 8) * XSTR + kb * 16 + tg * 4];
                a[mi][0] = lo.x; a[mi][1] = hi.x; a[mi][2] = lo.y; a[mi][3] = hi.y;
            }
            #pragma unroll
            for (int ni = 0; ni < 12; ni++) {
                uint2 bb = *(const uint2*)&Bs[(wn + ni * 8 + gid) * XSTR + kb * 16 + tg * 4];
                MMA_F16(acc[0][ni], a[0], bb.x, bb.y);
                MMA_F16(acc[1][ni], a[1], bb.x, bb.y);
            }
        }

        if (c + 1 < NCH) sstoreA(s ^ 1);
        __syncthreads();
    }

    // ---- epilogue: stage fp16 tiles (aliasing smem), coalesced copy out
    __half* stQ = smh;            // [t 128][h' 64]
    __half* stK = smh + 8192;
    __half* stV = smh + 16384;    // [h 64][t' 128]

    #pragma unroll
    for (int mi = 0; mi < 2; mi++) {
        #pragma unroll
        for (int ni = 0; ni < 12; ni++) {
            const int n   = wn + ni * 8 + tg * 2;
            const int sec = n >> 6;
            const int h   = n & 63;
            const int tl  = wm + mi * 16 + gid;
            float a0 = acc[mi][ni][0], a1 = acc[mi][ni][1];
            float a2 = acc[mi][ni][2], a3 = acc[mi][ni][3];
            if (sec == 2) {                      // V: transpose + t-interleave
                const int x0 = ih(tl), x1 = ih(tl + 8);
                stV[h * 128 + x0]       = __float2half(a0);
                stV[(h + 1) * 128 + x0] = __float2half(a1);
                stV[h * 128 + x1]       = __float2half(a2);
                stV[(h + 1) * 128 + x1] = __float2half(a3);
            } else {                             // Q/K: [t][h'] pair-interleaved
                __half* st = (sec == 0) ? stQ : stK;
                const float sc = (sec == 0) ? 0.125f : 1.0f;
                const int hp = ih(h);
                *(__half2*)&st[tl * 64 + hp]       = __floats2half2_rn(a0 * sc, a1 * sc);
                *(__half2*)&st[(tl + 8) * 64 + hp] = __floats2half2_rn(a2 * sc, a3 * sc);
            }
        }
    }
    __syncthreads();

    const int bb = m0 / TDIM;
    const int t0 = m0 % TDIM;
    #pragma unroll
    for (int i = 0; i < 4; i++) {
        int idx = tid + i * 256;                 // 1024 uint4 chunks
        int row = idx >> 3, c = idx & 7;
        *(uint4*)(g_Qh + (size_t)(m0 + row) * 64 + c * 8) =
            *(uint4*)(stQ + row * 64 + c * 8);
        *(uint4*)(g_Kh + (size_t)(m0 + row) * 64 + c * 8) =
            *(uint4*)(stK + row * 64 + c * 8);
    }
    #pragma unroll
    for (int i = 0; i < 4; i++) {
        int idx = tid + i * 256;                 // 1024 uint4 chunks (64 x 16)
        int h = idx >> 4, c = idx & 15;
        *(uint4*)(g_Vh + ((size_t)bb * 64 + h) * TDIM + t0 + c * 8) =
            *(uint4*)(stV + h * 128 + c * 8);
    }
}

// ---------------------------------------------------------------------------
// Kernel 2: flash attention, fp16 m16n8k16, P in registers.
// CTA = 128 q rows, 8 warps x 16 rows; KV tiles 64 (2x reuse per KV load).
// ---------------------------------------------------------------------------
#define KVS 80

__global__ __launch_bounds__(256, 2) void attn_f16(float* __restrict__ out)
{
    __shared__ __half Ks[64 * KVS];   // [j][h']  10 KB
    __shared__ __half Vs[64 * KVS];   // [h][j']  10 KB

    const int b    = blockIdx.y;
    const int qt   = gridDim.x - 1 - blockIdx.x;   // heavy q-tiles first
    const int tid  = threadIdx.x;
    const int wid  = tid >> 5;
    const int lane = tid & 31;
    const int gid  = lane >> 2;
    const int tg   = lane & 3;
    const int wm   = wid * 16;
    const int q0   = qt * 128;
    const int row0 = q0 + wm + gid;

    uint32_t qa[4][4];
    {
        const __half* Qh = g_Qh + ((size_t)b * TDIM + q0 + wm) * 64;
        #pragma unroll
        for (int kb = 0; kb < 4; kb++) {
            uint2 lo = *(const uint2*)(Qh + gid * 64 + 16 * kb + 4 * tg);
            uint2 hi = *(const uint2*)(Qh + (gid + 8) * 64 + 16 * kb + 4 * tg);
            qa[kb][0] = lo.x; qa[kb][1] = hi.x; qa[kb][2] = lo.y; qa[kb][3] = hi.y;
        }
    }

    float o[8][4];
    #pragma unroll
    for (int n = 0; n < 8; n++)
        #pragma unroll
        for (int k = 0; k < 4; k++) o[n][k] = 0.f;
    float m0r = -INFINITY, m1r = -INFINITY;
    float l0 = 0.f, l1 = 0.f;

    const uint32_t ksb = smem_u32(Ks);
    const uint32_t vsb = smem_u32(Vs);
    const int ntiles = 2 * qt + 2;

    for (int kt = 0; kt < ntiles; kt++) {
        const int kv0 = kt * 64;

        __syncthreads();
        {
            const __half* Kg = g_Kh + ((size_t)b * TDIM + kv0) * 64;
            const __half* Vg = g_Vh + (size_t)b * 64 * TDIM + kv0;
            #pragma unroll
            for (int i = 0; i < 2; i++) {
                int idx = tid + i * 256;          // 512 chunks of 16B
                int row = idx >> 3, c = idx & 7;
                cp16(ksb + row * (KVS * 2) + c * 16, Kg + (size_t)row * 64 + c * 8);
                cp16(vsb + row * (KVS * 2) + c * 16, Vg + (size_t)row * TDIM + c * 8);
            }
        }
        asm volatile("cp.async.commit_group;");
        asm volatile("cp.async.wait_group 0;" ::: "memory");
        __syncthreads();

        float s[8][4];
        #pragma unroll
        for (int n = 0; n < 8; n++) {
            s[n][0] = s[n][1] = s[n][2] = s[n][3] = 0.f;
            #pragma unroll
            for (int k = 0; k < 4; k++) {
                uint2 bb = *(const uint2*)(Ks + (n * 8 + gid) * KVS + 16 * k + 4 * tg);
                MMA_F16(s[n], qa[k], bb.x, bb.y);
            }
        }

        // Causal mask: the q-block spans two diagonal KV tiles (last two kt).
        if (kt >= ntiles - 2) {
            #pragma unroll
            for (int n = 0; n < 8; n++) {
                int j0 = kv0 + n * 8 + 2 * tg;
                if (j0     > row0)     s[n][0] = -1e30f;
                if (j0 + 1 > row0)     s[n][1] = -1e30f;
                if (j0     > row0 + 8) s[n][2] = -1e30f;
                if (j0 + 1 > row0 + 8) s[n][3] = -1e30f;
            }
        }

        float tm0 = -INFINITY, tm1 = -INFINITY;
        #pragma unroll
        for (int n = 0; n < 8; n++) {
            tm0 = fmaxf(tm0, fmaxf(s[n][0], s[n][1]));
            tm1 = fmaxf(tm1, fmaxf(s[n][2], s[n][3]));
        }
        tm0 = fmaxf(tm0, __shfl_xor_sync(0xFFFFFFFFu, tm0, 1));
        tm0 = fmaxf(tm0, __shfl_xor_sync(0xFFFFFFFFu, tm0, 2));
        tm1 = fmaxf(tm1, __shfl_xor_sync(0xFFFFFFFFu, tm1, 1));
        tm1 = fmaxf(tm1, __shfl_xor_sync(0xFFFFFFFFu, tm1, 2));

        const float mn0 = fmaxf(m0r, tm0);
        const float mn1 = fmaxf(m1r, tm1);
        const float c0  = __expf(m0r - mn0);
        const float c1  = __expf(m1r - mn1);
        l0 *= c0;  l1 *= c1;
        #pragma unroll
        for (int n = 0; n < 8; n++) {
            o[n][0] *= c0; o[n][1] *= c0;
            o[n][2] *= c1; o[n][3] *= c1;
        }
        m0r = mn0;  m1r = mn1;

        uint32_t pa[4][4];
        #pragma unroll
        for (int n = 0; n < 8; n++) {
            float p0 = __expf(s[n][0] - mn0);
            float p1 = __expf(s[n][1] - mn0);
            float p2 = __expf(s[n][2] - mn1);
            float p3 = __expf(s[n][3] - mn1);
            l0 += p0 + p1;
            l1 += p2 + p3;
            const int kl = n >> 1;
            if ((n & 1) == 0) { pa[kl][0] = h2u(p0, p1); pa[kl][1] = h2u(p2, p3); }
            else              { pa[kl][2] = h2u(p0, p1); pa[kl][3] = h2u(p2, p3); }
        }

        #pragma unroll
        for (int n = 0; n < 8; n++) {
            #pragma unroll
            for (int kl = 0; kl < 4; kl++) {
                uint2 bb = *(const uint2*)(Vs + (n * 8 + gid) * KVS + 16 * kl + 4 * tg);
                MMA_F16(o[n], pa[kl], bb.x, bb.y);
            }
        }
    }

    l0 += __shfl_xor_sync(0xFFFFFFFFu, l0, 1);
    l0 += __shfl_xor_sync(0xFFFFFFFFu, l0, 2);
    l1 += __shfl_xor_sync(0xFFFFFFFFu, l1, 1);
    l1 += __shfl_xor_sync(0xFFFFFFFFu, l1, 2);
    const float i0 = 1.f / l0;
    const float i1 = 1.f / l1;

    float* ob = out + ((size_t)b * TDIM + q0 + wm) * HDIM;
    #pragma unroll
    for (int n = 0; n < 8; n++) {
        *(float2*)&ob[gid * HDIM + n * 8 + 2 * tg] =
            make_float2(o[n][0] * i0, o[n][1] * i0);
        *(float2*)&ob[(gid + 8) * HDIM + n * 8 + 2 * tg] =
            make_float2(o[n][2] * i1, o[n][3] * i1);
    }
}

// ---------------------------------------------------------------------------
extern "C" void kernel_launch(void* const* d_in, const int* in_sizes, int n_in,
                              void* d_out, int out_size)
{
    const float* x  = (const float*)d_in[0];
    const float* wq = (const float*)d_in[1];
    const float* wk = (const float*)d_in[2];
    const float* wv = (const float*)d_in[3];
    float* out = (float*)d_out;

    cvt_w<<<24, 256>>>(wq, wk, wv);

    cudaFuncSetAttribute(qkv_proj_f16, cudaFuncAttributeMaxDynamicSharedMemorySize, PROJ_SMEM);
    qkv_proj_f16<<<MROWS / 128, 256, PROJ_SMEM>>>(x);

    attn_f16<<<dim3(TDIM / 128, BDIM), 256>>>(out);
}

// round 12
// speedup vs baseline: 1.1432x; 1.1205x over previous
#include <cuda_runtime.h>
#include <cuda_fp16.h>
#include <math.h>
#include <cstdint>

#define BDIM 16
#define TDIM 2048
#define CDIM 1024
#define HDIM 64
#define MROWS (BDIM * TDIM)   // 32768

// fp16 scratch (device globals: no allocations).
__device__ __align__(16) __half g_Qh[MROWS * HDIM];                // [t][h'] interleaved, pre-scaled
__device__ __align__(16) __half g_Kh[MROWS * HDIM];                // [t][h'] interleaved
__device__ __align__(16) __half g_Vh[(size_t)BDIM * HDIM * TDIM];  // [b][h][t'] interleaved
__device__ __align__(16) __half g_Wh[192 * CDIM];                  // [n][k'] interleaved

// pair interleave within 16-groups: x=(a+8b+16c), a<8,b<2 -> 4*((a>>1)&3)+(a&1)+2b+16c
static __device__ __forceinline__ int ih(int x) {
    return 4 * ((x >> 1) & 3) + (x & 1) + 2 * ((x >> 3) & 1) + (x & ~15);
}
static __device__ __forceinline__ uint32_t h2u(float lo, float hi) {
    __half2 h = __floats2half2_rn(lo, hi);
    return *(uint32_t*)&h;
}
static __device__ __forceinline__ uint32_t smem_u32(const void* p) {
    uint32_t a;
    asm("{ .reg .u64 t; cvta.to.shared.u64 t, %1; cvt.u32.u64 %0, t; }" : "=r"(a) : "l"(p));
    return a;
}
static __device__ __forceinline__ void cp16(uint32_t saddr, const void* g) {
    asm volatile("cp.async.ca.shared.global [%0], [%1], 16;" :: "r"(saddr), "l"(g));
}

#define MMA_F16(d, a, b0_, b1_) \
    asm volatile( \
        "mma.sync.aligned.m16n8k16.row.col.f32.f16.f16.f32 " \
        "{%0,%1,%2,%3}, {%4,%5,%6,%7}, {%8,%9}, {%0,%1,%2,%3};" \
        : "+f"((d)[0]), "+f"((d)[1]), "+f"((d)[2]), "+f"((d)[3]) \
        : "r"((a)[0]), "r"((a)[1]), "r"((a)[2]), "r"((a)[3]), \
          "r"(b0_), "r"(b1_))

// ---------------------------------------------------------------------------
// Kernel 0: convert weights to fp16 [n][k'] interleaved — coalesced transpose.
// Grid: 3 matrices x 16 k-blocks of 64.
// ---------------------------------------------------------------------------
__global__ __launch_bounds__(256) void cvt_w(
    const float* __restrict__ wq,
    const float* __restrict__ wk,
    const float* __restrict__ wv)
{
    __shared__ float ws[64][65];         // [k][n] padded

    const int widx = blockIdx.x >> 4;
    const int kblk = (blockIdx.x & 15) * 64;
    const float* wp = (widx == 0) ? wq : ((widx == 1) ? wk : wv);

    #pragma unroll
    for (int i = 0; i < 4; i++) {
        int idx = threadIdx.x + i * 256;       // 1024 float4 (64 rows x 16)
        int r = idx >> 4, c4 = idx & 15;
        float4 v = *(const float4*)&wp[(size_t)(kblk + r) * HDIM + c4 * 4];
        ws[r][c4 * 4 + 0] = v.x;
        ws[r][c4 * 4 + 1] = v.y;
        ws[r][c4 * 4 + 2] = v.z;
        ws[r][c4 * 4 + 3] = v.w;
    }
    __syncthreads();

    #pragma unroll
    for (int i = 0; i < 8; i++) {
        int idx = threadIdx.x + i * 256;       // 2048 half2 (64 n x 32 k-pairs)
        int nn = idx >> 5, kp = idx & 31;
        int kl = kp * 2;                       // even k: ih(k+1)=ih(k)+1
        *(__half2*)&g_Wh[(size_t)(widx * 64 + nn) * CDIM + ih(kblk + kl)] =
            __floats2half2_rn(ws[kl][nn], ws[kl + 1][nn]);
    }
}

// ---------------------------------------------------------------------------
// Kernel 1: QKV projection, fp16 m16n8k16 — R8 config (128x192, 256 thr).
// ---------------------------------------------------------------------------
#define XSTR 48                      // smem row stride in halfs
#define PA_H (128 * XSTR)            // A stage halfs (6144)
#define PB_H (192 * XSTR)            // B stage halfs (9216)
#define PROJ_SMEM ((2 * PA_H + 2 * PB_H) * 2)   // 61440 B
#define NCH (CDIM / 32)              // 32 chunks

__global__ __launch_bounds__(256) void qkv_proj_f16(const float* __restrict__ x)
{
    extern __shared__ __half smh[];
    __half* Ax = smh;                // [2][128*48]
    __half* Bw = smh + 2 * PA_H;     // [2][192*48]

    const int tid  = threadIdx.x;
    const int wid  = tid >> 5;
    const int lane = tid & 31;
    const int gid  = lane >> 2;
    const int tg   = lane & 3;
    const int wm   = (wid >> 1) * 32;
    const int wn   = (wid & 1) * 96;
    const int m0   = blockIdx.x * 128;
    const uint32_t bwb = smem_u32(Bw);

    float acc[2][12][4];
    #pragma unroll
    for (int mi = 0; mi < 2; mi++)
        #pragma unroll
        for (int ni = 0; ni < 12; ni++)
            #pragma unroll
            for (int k = 0; k < 4; k++) acc[mi][ni][k] = 0.f;

    float4 ra[4];

    auto gloadA = [&](int c) {
        #pragma unroll
        for (int i = 0; i < 4; i++) {
            int idx = tid + i * 256;             // 1024 float4 slots (128x32)
            int row = idx >> 3, c4 = idx & 7;
            ra[i] = *(const float4*)&x[(size_t)(m0 + row) * CDIM + c * 32 + c4 * 4];
        }
    };
    auto sstoreA = [&](int s) {
        #pragma unroll
        for (int i = 0; i < 4; i++) {
            int idx = tid + i * 256;
            int row = idx >> 3, c4 = idx & 7;
            int k = c4 * 4;
            __half* base = Ax + s * PA_H + row * XSTR;
            *(__half2*)&base[ih(k)]     = __floats2half2_rn(ra[i].x, ra[i].y);
            *(__half2*)&base[ih(k + 2)] = __floats2half2_rn(ra[i].z, ra[i].w);
        }
    };
    auto cpB = [&](int c, int s) {
        #pragma unroll
        for (int i = 0; i < 3; i++) {
            int idx = tid + i * 256;             // 768 16B chunks (192 rows x 4)
            int row = idx >> 2, cc = idx & 3;
            cp16(bwb + s * (PB_H * 2) + row * (XSTR * 2) + cc * 16,
                 g_Wh + (size_t)row * CDIM + c * 32 + cc * 8);
        }
    };

    gloadA(0);
    cpB(0, 0);
    asm volatile("cp.async.commit_group;");
    sstoreA(0);

    for (int c = 0; c < NCH; c++) {
        const int s = c & 1;
        if (c + 1 < NCH) {
            gloadA(c + 1);
            cpB(c + 1, s ^ 1);
            asm volatile("cp.async.commit_group;");
        }
        if (c + 1 < NCH) { asm volatile("cp.async.wait_group 1;" ::: "memory"); }
        else             { asm volatile("cp.async.wait_group 0;" ::: "memory"); }
        __syncthreads();

        const __half* As = Ax + s * PA_H;
        const __half* Bs = Bw + s * PB_H;
        #pragma unroll
        for (int kb = 0; kb < 2; kb++) {
            uint32_t a[2][4];
            #pragma unroll
            for (int mi = 0; mi < 2; mi++) {
                int row = wm + mi * 16 + gid;
                uint2 lo = *(const uint2*)&As[row * XSTR + kb * 16 + tg * 4];
                uint2 hi = *(const uint2*)&As[(row + 8) * XSTR + kb * 16 + tg * 4];
                a[mi][0] = lo.x; a[mi][1] = hi.x; a[mi][2] = lo.y; a[mi][3] = hi.y;
            }
            #pragma unroll
            for (int ni = 0; ni < 12; ni++) {
                uint2 bb = *(const uint2*)&Bs[(wn + ni * 8 + gid) * XSTR + kb * 16 + tg * 4];
                MMA_F16(acc[0][ni], a[0], bb.x, bb.y);
                MMA_F16(acc[1][ni], a[1], bb.x, bb.y);
            }
        }

        if (c + 1 < NCH) sstoreA(s ^ 1);
        __syncthreads();
    }

    // ---- epilogue: stage fp16 tiles (aliasing smem), coalesced copy out
    __half* stQ = smh;            // [t 128][h' 64]
    __half* stK = smh + 8192;
    __half* stV = smh + 16384;    // [h 64][t' 128]

    #pragma unroll
    for (int mi = 0; mi < 2; mi++) {
        #pragma unroll
        for (int ni = 0; ni < 12; ni++) {
            const int n   = wn + ni * 8 + tg * 2;
            const int sec = n >> 6;
            const int h   = n & 63;
            const int tl  = wm + mi * 16 + gid;
            float a0 = acc[mi][ni][0], a1 = acc[mi][ni][1];
            float a2 = acc[mi][ni][2], a3 = acc[mi][ni][3];
            if (sec == 2) {                      // V: transpose + t-interleave
                const int x0 = ih(tl), x1 = ih(tl + 8);
                stV[h * 128 + x0]       = __float2half(a0);
                stV[(h + 1) * 128 + x0] = __float2half(a1);
                stV[h * 128 + x1]       = __float2half(a2);
                stV[(h + 1) * 128 + x1] = __float2half(a3);
            } else {                             // Q/K: [t][h'] pair-interleaved
                __half* st = (sec == 0) ? stQ : stK;
                const float sc = (sec == 0) ? 0.125f : 1.0f;
                const int hp = ih(h);
                *(__half2*)&st[tl * 64 + hp]       = __floats2half2_rn(a0 * sc, a1 * sc);
                *(__half2*)&st[(tl + 8) * 64 + hp] = __floats2half2_rn(a2 * sc, a3 * sc);
            }
        }
    }
    __syncthreads();

    const int bb = m0 / TDIM;
    const int t0 = m0 % TDIM;
    #pragma unroll
    for (int i = 0; i < 4; i++) {
        int idx = tid + i * 256;                 // 1024 uint4 chunks
        int row = idx >> 3, c = idx & 7;
        *(uint4*)(g_Qh + (size_t)(m0 + row) * 64 + c * 8) =
            *(uint4*)(stQ + row * 64 + c * 8);
        *(uint4*)(g_Kh + (size_t)(m0 + row) * 64 + c * 8) =
            *(uint4*)(stK + row * 64 + c * 8);
    }
    #pragma unroll
    for (int i = 0; i < 4; i++) {
        int idx = tid + i * 256;                 // 1024 uint4 chunks (64 x 16)
        int h = idx >> 4, c = idx & 15;
        *(uint4*)(g_Vh + ((size_t)bb * 64 + h) * TDIM + t0 + c * 8) =
            *(uint4*)(stV + h * 128 + c * 8);
    }
}

// ---------------------------------------------------------------------------
// Kernel 2: flash attention, fp16 m16n8k16 (R8 shape: 64 q rows, 4 warps)
// + double-buffered cp.async KV pipeline (load k+1 overlaps compute k).
// ---------------------------------------------------------------------------
#define KVS 80
#define TILE_H (64 * KVS)            // halfs per K (or V) tile buffer

__global__ __launch_bounds__(128, 4) void attn_f16(float* __restrict__ out)
{
    __shared__ __half Ks[2][TILE_H];   // [j][h']  2 x 10 KB
    __shared__ __half Vs[2][TILE_H];   // [h][j']  2 x 10 KB

    const int b    = blockIdx.y;
    const int qt   = gridDim.x - 1 - blockIdx.x;   // heavy q-tiles first
    const int tid  = threadIdx.x;
    const int wid  = tid >> 5;
    const int lane = tid & 31;
    const int gid  = lane >> 2;
    const int tg   = lane & 3;
    const int wm   = wid * 16;
    const int q0   = qt * 64;
    const int row0 = q0 + wm + gid;

    uint32_t qa[4][4];
    {
        const __half* Qh = g_Qh + ((size_t)b * TDIM + q0 + wm) * 64;
        #pragma unroll
        for (int kb = 0; kb < 4; kb++) {
            uint2 lo = *(const uint2*)(Qh + gid * 64 + 16 * kb + 4 * tg);
            uint2 hi = *(const uint2*)(Qh + (gid + 8) * 64 + 16 * kb + 4 * tg);
            qa[kb][0] = lo.x; qa[kb][1] = hi.x; qa[kb][2] = lo.y; qa[kb][3] = hi.y;
        }
    }

    float o[8][4];
    #pragma unroll
    for (int n = 0; n < 8; n++)
        #pragma unroll
        for (int k = 0; k < 4; k++) o[n][k] = 0.f;
    float m0r = -INFINITY, m1r = -INFINITY;
    float l0 = 0.f, l1 = 0.f;

    const uint32_t ksb = smem_u32(Ks);
    const uint32_t vsb = smem_u32(Vs);
    const int ntiles = qt + 1;
    const __half* Kb = g_Kh + (size_t)b * TDIM * 64;
    const __half* Vb = g_Vh + (size_t)b * 64 * TDIM;

    auto loadKV = [&](int kt, int s) {
        const __half* Kg = Kb + (size_t)(kt * 64) * 64;
        const __half* Vg = Vb + kt * 64;
        const uint32_t ko = ksb + s * (TILE_H * 2);
        const uint32_t vo = vsb + s * (TILE_H * 2);
        #pragma unroll
        for (int i = 0; i < 4; i++) {
            int idx = tid + i * 128;             // 512 chunks of 16B each tile
            int row = idx >> 3, c = idx & 7;
            cp16(ko + row * (KVS * 2) + c * 16, Kg + (size_t)row * 64 + c * 8);
            cp16(vo + row * (KVS * 2) + c * 16, Vg + (size_t)row * TDIM + c * 8);
        }
        asm volatile("cp.async.commit_group;");
    };

    loadKV(0, 0);   // preload tile 0

    for (int kt = 0; kt < ntiles; kt++) {
        const int s = kt & 1;
        const int kv0 = kt * 64;

        if (kt + 1 < ntiles) {
            loadKV(kt + 1, s ^ 1);               // overlaps compute of tile kt
            asm volatile("cp.async.wait_group 1;" ::: "memory");
        } else {
            asm volatile("cp.async.wait_group 0;" ::: "memory");
        }
        __syncthreads();

        const __half* Kt = Ks[s];
        const __half* Vt = Vs[s];

        float sacc[8][4];
        #pragma unroll
        for (int n = 0; n < 8; n++) {
            sacc[n][0] = sacc[n][1] = sacc[n][2] = sacc[n][3] = 0.f;
            #pragma unroll
            for (int k = 0; k < 4; k++) {
                uint2 bb = *(const uint2*)(Kt + (n * 8 + gid) * KVS + 16 * k + 4 * tg);
                MMA_F16(sacc[n], qa[k], bb.x, bb.y);
            }
        }

        if (kt == qt) {                          // diagonal tile only
            #pragma unroll
            for (int n = 0; n < 8; n++) {
                int j0 = kv0 + n * 8 + 2 * tg;
                if (j0     > row0)     sacc[n][0] = -1e30f;
                if (j0 + 1 > row0)     sacc[n][1] = -1e30f;
                if (j0     > row0 + 8) sacc[n][2] = -1e30f;
                if (j0 + 1 > row0 + 8) sacc[n][3] = -1e30f;
            }
        }

        float tm0 = -INFINITY, tm1 = -INFINITY;
        #pragma unroll
        for (int n = 0; n < 8; n++) {
            tm0 = fmaxf(tm0, fmaxf(sacc[n][0], sacc[n][1]));
            tm1 = fmaxf(tm1, fmaxf(sacc[n][2], sacc[n][3]));
        }
        tm0 = fmaxf(tm0, __shfl_xor_sync(0xFFFFFFFFu, tm0, 1));
        tm0 = fmaxf(tm0, __shfl_xor_sync(0xFFFFFFFFu, tm0, 2));
        tm1 = fmaxf(tm1, __shfl_xor_sync(0xFFFFFFFFu, tm1, 1));
        tm1 = fmaxf(tm1, __shfl_xor_sync(0xFFFFFFFFu, tm1, 2));

        const float mn0 = fmaxf(m0r, tm0);
        const float mn1 = fmaxf(m1r, tm1);
        const float c0  = __expf(m0r - mn0);
        const float c1  = __expf(m1r - mn1);
        l0 *= c0;  l1 *= c1;
        #pragma unroll
        for (int n = 0; n < 8; n++) {
            o[n][0] *= c0; o[n][1] *= c0;
            o[n][2] *= c1; o[n][3] *= c1;
        }
        m0r = mn0;  m1r = mn1;

        uint32_t pa[4][4];
        #pragma unroll
        for (int n = 0; n < 8; n++) {
            float p0 = __expf(sacc[n][0] - mn0);
            float p1 = __expf(sacc[n][1] - mn0);
            float p2 = __expf(sacc[n][2] - mn1);
            float p3 = __expf(sacc[n][3] - mn1);
            l0 += p0 + p1;
            l1 += p2 + p3;
            const int kl = n >> 1;
            if ((n & 1) == 0) { pa[kl][0] = h2u(p0, p1); pa[kl][1] = h2u(p2, p3); }
            else              { pa[kl][2] = h2u(p0, p1); pa[kl][3] = h2u(p2, p3); }
        }

        #pragma unroll
        for (int n = 0; n < 8; n++) {
            #pragma unroll
            for (int kl = 0; kl < 4; kl++) {
                uint2 bb = *(const uint2*)(Vt + (n * 8 + gid) * KVS + 16 * kl + 4 * tg);
                MMA_F16(o[n], pa[kl], bb.x, bb.y);
            }
        }
        __syncthreads();   // all warps done with buf s before it is overwritten
    }

    l0 += __shfl_xor_sync(0xFFFFFFFFu, l0, 1);
    l0 += __shfl_xor_sync(0xFFFFFFFFu, l0, 2);
    l1 += __shfl_xor_sync(0xFFFFFFFFu, l1, 1);
    l1 += __shfl_xor_sync(0xFFFFFFFFu, l1, 2);
    const float i0 = 1.f / l0;
    const float i1 = 1.f / l1;

    float* ob = out + ((size_t)b * TDIM + q0 + wm) * HDIM;
    #pragma unroll
    for (int n = 0; n < 8; n++) {
        *(float2*)&ob[gid * HDIM + n * 8 + 2 * tg] =
            make_float2(o[n][0] * i0, o[n][1] * i0);
        *(float2*)&ob[(gid + 8) * HDIM + n * 8 + 2 * tg] =
            make_float2(o[n][2] * i1, o[n][3] * i1);
    }
}

// ---------------------------------------------------------------------------
extern "C" void kernel_launch(void* const* d_in, const int* in_sizes, int n_in,
                              void* d_out, int out_size)
{
    const float* x  = (const float*)d_in[0];
    const float* wq = (const float*)d_in[1];
    const float* wk = (const float*)d_in[2];
    const float* wv = (const float*)d_in[3];
    float* out = (float*)d_out;

    cvt_w<<<48, 256>>>(wq, wk, wv);

    cudaFuncSetAttribute(qkv_proj_f16, cudaFuncAttributeMaxDynamicSharedMemorySize, PROJ_SMEM);
    qkv_proj_f16<<<MROWS / 128, 256, PROJ_SMEM>>>(x);

    attn_f16<<<dim3(TDIM / 64, BDIM), 128>>>(out);
}

// round 13
// speedup vs baseline: 1.1854x; 1.0369x over previous
#include <cuda_runtime.h>
#include <cuda_fp16.h>
#include <math.h>
#include <cstdint>

#define BDIM 16
#define TDIM 2048
#define CDIM 1024
#define HDIM 64
#define MROWS (BDIM * TDIM)   // 32768

// fp16 scratch (device globals: no allocations).
__device__ __align__(16) __half g_Qh[MROWS * HDIM];                // [t][h'] interleaved, pre-scaled
__device__ __align__(16) __half g_Kh[MROWS * HDIM];                // [t][h'] interleaved
__device__ __align__(16) __half g_Vh[(size_t)BDIM * HDIM * TDIM];  // [b][h][t'] interleaved
__device__ __align__(16) __half g_Wh[192 * CDIM];                  // [n][k'] interleaved

// pair interleave within 16-groups: x=(a+8b+16c), a<8,b<2 -> 4*((a>>1)&3)+(a&1)+2b+16c
static __device__ __forceinline__ int ih(int x) {
    return 4 * ((x >> 1) & 3) + (x & 1) + 2 * ((x >> 3) & 1) + (x & ~15);
}
static __device__ __forceinline__ uint32_t h2u(float lo, float hi) {
    __half2 h = __floats2half2_rn(lo, hi);
    return *(uint32_t*)&h;
}
static __device__ __forceinline__ uint32_t smem_u32(const void* p) {
    uint32_t a;
    asm("{ .reg .u64 t; cvta.to.shared.u64 t, %1; cvt.u32.u64 %0, t; }" : "=r"(a) : "l"(p));
    return a;
}
static __device__ __forceinline__ void cp16(uint32_t saddr, const void* g) {
    asm volatile("cp.async.ca.shared.global [%0], [%1], 16;" :: "r"(saddr), "l"(g));
}

#define MMA_F16(d, a, b0_, b1_) \
    asm volatile( \
        "mma.sync.aligned.m16n8k16.row.col.f32.f16.f16.f32 " \
        "{%0,%1,%2,%3}, {%4,%5,%6,%7}, {%8,%9}, {%0,%1,%2,%3};" \
        : "+f"((d)[0]), "+f"((d)[1]), "+f"((d)[2]), "+f"((d)[3]) \
        : "r"((a)[0]), "r"((a)[1]), "r"((a)[2]), "r"((a)[3]), \
          "r"(b0_), "r"(b1_))

// ---------------------------------------------------------------------------
// Kernel 0: convert weights to fp16 [n][k'] interleaved — coalesced transpose.
// ---------------------------------------------------------------------------
__global__ __launch_bounds__(256) void cvt_w(
    const float* __restrict__ wq,
    const float* __restrict__ wk,
    const float* __restrict__ wv)
{
    __shared__ float ws[64][65];         // [k][n] padded

    const int widx = blockIdx.x >> 4;
    const int kblk = (blockIdx.x & 15) * 64;
    const float* wp = (widx == 0) ? wq : ((widx == 1) ? wk : wv);

    #pragma unroll
    for (int i = 0; i < 4; i++) {
        int idx = threadIdx.x + i * 256;       // 1024 float4 (64 rows x 16)
        int r = idx >> 4, c4 = idx & 15;
        float4 v = *(const float4*)&wp[(size_t)(kblk + r) * HDIM + c4 * 4];
        ws[r][c4 * 4 + 0] = v.x;
        ws[r][c4 * 4 + 1] = v.y;
        ws[r][c4 * 4 + 2] = v.z;
        ws[r][c4 * 4 + 3] = v.w;
    }
    __syncthreads();

    #pragma unroll
    for (int i = 0; i < 8; i++) {
        int idx = threadIdx.x + i * 256;       // 2048 half2 (64 n x 32 k-pairs)
        int nn = idx >> 5, kp = idx & 31;
        int kl = kp * 2;                       // even k: ih(k+1)=ih(k)+1
        *(__half2*)&g_Wh[(size_t)(widx * 64 + nn) * CDIM + ih(kblk + kl)] =
            __floats2half2_rn(ws[kl][nn], ws[kl + 1][nn]);
    }
}

// ---------------------------------------------------------------------------
// Kernel 1: QKV projection, fp16 m16n8k16.
// CTA tile 128x192 (unchanged). 512 threads, 16 warps, warp tile 32x48:
// same smem traffic/reuse, 2x issue parallelism per SMSP.
// ---------------------------------------------------------------------------
#define XSTR 48                      // smem row stride in halfs
#define PA_H (128 * XSTR)            // A stage halfs (6144)
#define PB_H (192 * XSTR)            // B stage halfs (9216)
#define PROJ_SMEM ((2 * PA_H + 2 * PB_H) * 2)   // 61440 B
#define NCH (CDIM / 32)              // 32 chunks

__global__ __launch_bounds__(512) void qkv_proj_f16(const float* __restrict__ x)
{
    extern __shared__ __half smh[];
    __half* Ax = smh;                // [2][128*48]
    __half* Bw = smh + 2 * PA_H;     // [2][192*48]

    const int tid  = threadIdx.x;
    const int wid  = tid >> 5;
    const int lane = tid & 31;
    const int gid  = lane >> 2;
    const int tg   = lane & 3;
    const int wm   = (wid >> 2) * 32;      // 4 m-strips of 32
    const int wn   = (wid & 3) * 48;       // 4 n-strips of 48
    const int m0   = blockIdx.x * 128;
    const uint32_t bwb = smem_u32(Bw);

    float acc[2][6][4];
    #pragma unroll
    for (int mi = 0; mi < 2; mi++)
        #pragma unroll
        for (int ni = 0; ni < 6; ni++)
            #pragma unroll
            for (int k = 0; k < 4; k++) acc[mi][ni][k] = 0.f;

    float4 ra[2];

    auto gloadA = [&](int c) {
        #pragma unroll
        for (int i = 0; i < 2; i++) {
            int idx = tid + i * 512;             // 1024 float4 slots (128x32)
            int row = idx >> 3, c4 = idx & 7;
            ra[i] = *(const float4*)&x[(size_t)(m0 + row) * CDIM + c * 32 + c4 * 4];
        }
    };
    auto sstoreA = [&](int s) {
        #pragma unroll
        for (int i = 0; i < 2; i++) {
            int idx = tid + i * 512;
            int row = idx >> 3, c4 = idx & 7;
            int k = c4 * 4;
            __half* base = Ax + s * PA_H + row * XSTR;
            *(__half2*)&base[ih(k)]     = __floats2half2_rn(ra[i].x, ra[i].y);
            *(__half2*)&base[ih(k + 2)] = __floats2half2_rn(ra[i].z, ra[i].w);
        }
    };
    auto cpB = [&](int c, int s) {
        #pragma unroll
        for (int i = 0; i < 2; i++) {
            int idx = tid + i * 512;             // 768 16B chunks (192 rows x 4)
            if (idx < 768) {
                int row = idx >> 2, cc = idx & 3;
                cp16(bwb + s * (PB_H * 2) + row * (XSTR * 2) + cc * 16,
                     g_Wh + (size_t)row * CDIM + c * 32 + cc * 8);
            }
        }
    };

    gloadA(0);
    cpB(0, 0);
    asm volatile("cp.async.commit_group;");
    sstoreA(0);

    for (int c = 0; c < NCH; c++) {
        const int s = c & 1;
        if (c + 1 < NCH) {
            gloadA(c + 1);
            cpB(c + 1, s ^ 1);
            asm volatile("cp.async.commit_group;");
        }
        if (c + 1 < NCH) { asm volatile("cp.async.wait_group 1;" ::: "memory"); }
        else             { asm volatile("cp.async.wait_group 0;" ::: "memory"); }
        __syncthreads();

        const __half* As = Ax + s * PA_H;
        const __half* Bs = Bw + s * PB_H;
        #pragma unroll
        for (int kb = 0; kb < 2; kb++) {
            uint32_t a[2][4];
            #pragma unroll
            for (int mi = 0; mi < 2; mi++) {
                int row = wm + mi * 16 + gid;
                uint2 lo = *(const uint2*)&As[row * XSTR + kb * 16 + tg * 4];
                uint2 hi = *(const uint2*)&As[(row + 8) * XSTR + kb * 16 + tg * 4];
                a[mi][0] = lo.x; a[mi][1] = hi.x; a[mi][2] = lo.y; a[mi][3] = hi.y;
            }
            #pragma unroll
            for (int ni = 0; ni < 6; ni++) {
                uint2 bb = *(const uint2*)&Bs[(wn + ni * 8 + gid) * XSTR + kb * 16 + tg * 4];
                MMA_F16(acc[0][ni], a[0], bb.x, bb.y);
                MMA_F16(acc[1][ni], a[1], bb.x, bb.y);
            }
        }

        if (c + 1 < NCH) sstoreA(s ^ 1);
        __syncthreads();
    }

    // ---- epilogue: stage fp16 tiles (aliasing smem), coalesced copy out
    __half* stQ = smh;            // [t 128][h' 64]
    __half* stK = smh + 8192;
    __half* stV = smh + 16384;    // [h 64][t' 128]

    #pragma unroll
    for (int mi = 0; mi < 2; mi++) {
        #pragma unroll
        for (int ni = 0; ni < 6; ni++) {
            const int n   = wn + ni * 8 + tg * 2;
            const int sec = n >> 6;
            const int h   = n & 63;
            const int tl  = wm + mi * 16 + gid;
            float a0 = acc[mi][ni][0], a1 = acc[mi][ni][1];
            float a2 = acc[mi][ni][2], a3 = acc[mi][ni][3];
            if (sec == 2) {                      // V: transpose + t-interleave
                const int x0 = ih(tl), x1 = ih(tl + 8);
                stV[h * 128 + x0]       = __float2half(a0);
                stV[(h + 1) * 128 + x0] = __float2half(a1);
                stV[h * 128 + x1]       = __float2half(a2);
                stV[(h + 1) * 128 + x1] = __float2half(a3);
            } else {                             // Q/K: [t][h'] pair-interleaved
                __half* st = (sec == 0) ? stQ : stK;
                const float sc = (sec == 0) ? 0.125f : 1.0f;
                const int hp = ih(h);
                *(__half2*)&st[tl * 64 + hp]       = __floats2half2_rn(a0 * sc, a1 * sc);
                *(__half2*)&st[(tl + 8) * 64 + hp] = __floats2half2_rn(a2 * sc, a3 * sc);
            }
        }
    }
    __syncthreads();

    const int bb = m0 / TDIM;
    const int t0 = m0 % TDIM;
    #pragma unroll
    for (int i = 0; i < 2; i++) {
        int idx = tid + i * 512;                 // 1024 uint4 chunks
        int row = idx >> 3, c = idx & 7;
        *(uint4*)(g_Qh + (size_t)(m0 + row) * 64 + c * 8) =
            *(uint4*)(stQ + row * 64 + c * 8);
        *(uint4*)(g_Kh + (size_t)(m0 + row) * 64 + c * 8) =
            *(uint4*)(stK + row * 64 + c * 8);
    }
    #pragma unroll
    for (int i = 0; i < 2; i++) {
        int idx = tid + i * 512;                 // 1024 uint4 chunks (64 x 16)
        int h = idx >> 4, c = idx & 15;
        *(uint4*)(g_Vh + ((size_t)bb * 64 + h) * TDIM + t0 + c * 8) =
            *(uint4*)(stV + h * 128 + c * 8);
    }
}

// ---------------------------------------------------------------------------
// Kernel 2: flash attention, fp16 m16n8k16 (R11: 64 q rows, 4 warps,
// double-buffered cp.async KV pipeline). Unchanged.
// ---------------------------------------------------------------------------
#define KVS 80
#define TILE_H (64 * KVS)            // halfs per K (or V) tile buffer

__global__ __launch_bounds__(128, 4) void attn_f16(float* __restrict__ out)
{
    __shared__ __half Ks[2][TILE_H];   // [j][h']  2 x 10 KB
    __shared__ __half Vs[2][TILE_H];   // [h][j']  2 x 10 KB

    const int b    = blockIdx.y;
    const int qt   = gridDim.x - 1 - blockIdx.x;   // heavy q-tiles first
    const int tid  = threadIdx.x;
    const int wid  = tid >> 5;
    const int lane = tid & 31;
    const int gid  = lane >> 2;
    const int tg   = lane & 3;
    const int wm   = wid * 16;
    const int q0   = qt * 64;
    const int row0 = q0 + wm + gid;

    uint32_t qa[4][4];
    {
        const __half* Qh = g_Qh + ((size_t)b * TDIM + q0 + wm) * 64;
        #pragma unroll
        for (int kb = 0; kb < 4; kb++) {
            uint2 lo = *(const uint2*)(Qh + gid * 64 + 16 * kb + 4 * tg);
            uint2 hi = *(const uint2*)(Qh + (gid + 8) * 64 + 16 * kb + 4 * tg);
            qa[kb][0] = lo.x; qa[kb][1] = hi.x; qa[kb][2] = lo.y; qa[kb][3] = hi.y;
        }
    }

    float o[8][4];
    #pragma unroll
    for (int n = 0; n < 8; n++)
        #pragma unroll
        for (int k = 0; k < 4; k++) o[n][k] = 0.f;
    float m0r = -INFINITY, m1r = -INFINITY;
    float l0 = 0.f, l1 = 0.f;

    const uint32_t ksb = smem_u32(Ks);
    const uint32_t vsb = smem_u32(Vs);
    const int ntiles = qt + 1;
    const __half* Kb = g_Kh + (size_t)b * TDIM * 64;
    const __half* Vb = g_Vh + (size_t)b * 64 * TDIM;

    auto loadKV = [&](int kt, int s) {
        const __half* Kg = Kb + (size_t)(kt * 64) * 64;
        const __half* Vg = Vb + kt * 64;
        const uint32_t ko = ksb + s * (TILE_H * 2);
        const uint32_t vo = vsb + s * (TILE_H * 2);
        #pragma unroll
        for (int i = 0; i < 4; i++) {
            int idx = tid + i * 128;             // 512 chunks of 16B each tile
            int row = idx >> 3, c = idx & 7;
            cp16(ko + row * (KVS * 2) + c * 16, Kg + (size_t)row * 64 + c * 8);
            cp16(vo + row * (KVS * 2) + c * 16, Vg + (size_t)row * TDIM + c * 8);
        }
        asm volatile("cp.async.commit_group;");
    };

    loadKV(0, 0);   // preload tile 0

    for (int kt = 0; kt < ntiles; kt++) {
        const int s = kt & 1;
        const int kv0 = kt * 64;

        if (kt + 1 < ntiles) {
            loadKV(kt + 1, s ^ 1);               // overlaps compute of tile kt
            asm volatile("cp.async.wait_group 1;" ::: "memory");
        } else {
            asm volatile("cp.async.wait_group 0;" ::: "memory");
        }
        __syncthreads();

        const __half* Kt = Ks[s];
        const __half* Vt = Vs[s];

        float sacc[8][4];
        #pragma unroll
        for (int n = 0; n < 8; n++) {
            sacc[n][0] = sacc[n][1] = sacc[n][2] = sacc[n][3] = 0.f;
            #pragma unroll
            for (int k = 0; k < 4; k++) {
                uint2 bb = *(const uint2*)(Kt + (n * 8 + gid) * KVS + 16 * k + 4 * tg);
                MMA_F16(sacc[n], qa[k], bb.x, bb.y);
            }
        }

        if (kt == qt) {                          // diagonal tile only
            #pragma unroll
            for (int n = 0; n < 8; n++) {
                int j0 = kv0 + n * 8 + 2 * tg;
                if (j0     > row0)     sacc[n][0] = -1e30f;
                if (j0 + 1 > row0)     sacc[n][1] = -1e30f;
                if (j0     > row0 + 8) sacc[n][2] = -1e30f;
                if (j0 + 1 > row0 + 8) sacc[n][3] = -1e30f;
            }
        }

        float tm0 = -INFINITY, tm1 = -INFINITY;
        #pragma unroll
        for (int n = 0; n < 8; n++) {
            tm0 = fmaxf(tm0, fmaxf(sacc[n][0], sacc[n][1]));
            tm1 = fmaxf(tm1, fmaxf(sacc[n][2], sacc[n][3]));
        }
        tm0 = fmaxf(tm0, __shfl_xor_sync(0xFFFFFFFFu, tm0, 1));
        tm0 = fmaxf(tm0, __shfl_xor_sync(0xFFFFFFFFu, tm0, 2));
        tm1 = fmaxf(tm1, __shfl_xor_sync(0xFFFFFFFFu, tm1, 1));
        tm1 = fmaxf(tm1, __shfl_xor_sync(0xFFFFFFFFu, tm1, 2));

        const float mn0 = fmaxf(m0r, tm0);
        const float mn1 = fmaxf(m1r, tm1);
        const float c0  = __expf(m0r - mn0);
        const float c1  = __expf(m1r - mn1);
        l0 *= c0;  l1 *= c1;
        #pragma unroll
        for (int n = 0; n < 8; n++) {
            o[n][0] *= c0; o[n][1] *= c0;
            o[n][2] *= c1; o[n][3] *= c1;
        }
        m0r = mn0;  m1r = mn1;

        uint32_t pa[4][4];
        #pragma unroll
        for (int n = 0; n < 8; n++) {
            float p0 = __expf(sacc[n][0] - mn0);
            float p1 = __expf(sacc[n][1] - mn0);
            float p2 = __expf(sacc[n][2] - mn1);
            float p3 = __expf(sacc[n][3] - mn1);
            l0 += p0 + p1;
            l1 += p2 + p3;
            const int kl = n >> 1;
            if ((n & 1) == 0) { pa[kl][0] = h2u(p0, p1); pa[kl][1] = h2u(p2, p3); }
            else              { pa[kl][2] = h2u(p0, p1); pa[kl][3] = h2u(p2, p3); }
        }

        #pragma unroll
        for (int n = 0; n < 8; n++) {
            #pragma unroll
            for (int kl = 0; kl < 4; kl++) {
                uint2 bb = *(const uint2*)(Vt + (n * 8 + gid) * KVS + 16 * kl + 4 * tg);
                MMA_F16(o[n], pa[kl], bb.x, bb.y);
            }
        }
        __syncthreads();   // all warps done with buf s before it is overwritten
    }

    l0 += __shfl_xor_sync(0xFFFFFFFFu, l0, 1);
    l0 += __shfl_xor_sync(0xFFFFFFFFu, l0, 2);
    l1 += __shfl_xor_sync(0xFFFFFFFFu, l1, 1);
    l1 += __shfl_xor_sync(0xFFFFFFFFu, l1, 2);
    const float i0 = 1.f / l0;
    const float i1 = 1.f / l1;

    float* ob = out + ((size_t)b * TDIM + q0 + wm) * HDIM;
    #pragma unroll
    for (int n = 0; n < 8; n++) {
        *(float2*)&ob[gid * HDIM + n * 8 + 2 * tg] =
            make_float2(o[n][0] * i0, o[n][1] * i0);
        *(float2*)&ob[(gid + 8) * HDIM + n * 8 + 2 * tg] =
            make_float2(o[n][2] * i1, o[n][3] * i1);
    }
}

// ---------------------------------------------------------------------------
extern "C" void kernel_launch(void* const* d_in, const int* in_sizes, int n_in,
                              void* d_out, int out_size)
{
    const float* x  = (const float*)d_in[0];
    const float* wq = (const float*)d_in[1];
    const float* wk = (const float*)d_in[2];
    const float* wv = (const float*)d_in[3];
    float* out = (float*)d_out;

    cvt_w<<<48, 256>>>(wq, wk, wv);

    cudaFuncSetAttribute(qkv_proj_f16, cudaFuncAttributeMaxDynamicSharedMemorySize, PROJ_SMEM);
    qkv_proj_f16<<<MROWS / 128, 512, PROJ_SMEM>>>(x);

    attn_f16<<<dim3(TDIM / 64, BDIM), 128>>>(out);
}